// round 10
// baseline (speedup 1.0000x reference)
#include <cuda_runtime.h>
#include <cuda_bf16.h>
#include <cstdint>

// Problem dims (fixed by the reference setup_inputs)
#define MM   8192      // B*S = 4*2048
#define NN   4096      // D_OUT
#define KK   4096      // D_IN
#define RR   16        // LoRA rank
#define LORA_SCALING 2.0f   // alpha/r = 32/16

// ---------------------------------------------------------------------------
// Device scratch (static __device__ arrays — allowed; no runtime allocation)
// ---------------------------------------------------------------------------
__device__ float g_Weff[(size_t)NN * KK];   // 64 MB: fused dequant + LoRA, tf32-rounded
__device__ float g_xr  [(size_t)MM * KK];   // 128 MB: x rounded to tf32

// ---------------------------------------------------------------------------
// Helpers
// ---------------------------------------------------------------------------
__device__ __forceinline__ float to_tf32(float x) {
    unsigned u;
    asm("cvt.rna.tf32.f32 %0, %1;" : "=r"(u) : "f"(x));
    return __uint_as_float(u);
}

#define CP_ASYNC16(dst_u32, src_ptr) \
    asm volatile("cp.async.cg.shared.global [%0], [%1], 16;\n" :: "r"(dst_u32), "l"(src_ptr))
#define CP_COMMIT()  asm volatile("cp.async.commit_group;\n" ::)
#define CP_WAIT0()   asm volatile("cp.async.wait_group 0;\n" ::)

// ---------------------------------------------------------------------------
// Kernel 1: round x -> tf32 into g_xr (vectorized)
// ---------------------------------------------------------------------------
__global__ void conv_x_kernel(const float4* __restrict__ x) {
    size_t i = (size_t)blockIdx.x * blockDim.x + threadIdx.x;
    size_t n4 = (size_t)MM * KK / 4;
    if (i < n4) {
        float4 v = x[i];
        v.x = to_tf32(v.x); v.y = to_tf32(v.y);
        v.z = to_tf32(v.z); v.w = to_tf32(v.w);
        ((float4*)g_xr)[i] = v;
    }
}

// ---------------------------------------------------------------------------
// Kernel 2: build W_eff = (wq - zero)*scale + 2 * B @ A   (tf32-rounded)
//   wq:    [NN, KK] int32
//   scale: [NN, 1], zero: [NN, 1]
//   lA:    [RR, KK], lB: [NN, RR]
// Tiled: BO=64 output rows x BI=256 input cols per block.
// ---------------------------------------------------------------------------
__global__ void build_weff_kernel(const int* __restrict__ wq,
                                  const float* __restrict__ scale,
                                  const float* __restrict__ zero,
                                  const float* __restrict__ lA,
                                  const float* __restrict__ lB) {
    constexpr int BO = 64, BI = 256;
    __shared__ float sA[RR][BI];     // lA tile
    __shared__ float sB[BO][RR];     // lB tile
    __shared__ float sS[BO], sZ[BO];

    const int i0 = blockIdx.x * BI;
    const int o0 = blockIdx.y * BO;
    const int tid = threadIdx.x;      // 256 threads

    for (int idx = tid; idx < RR * BI; idx += 256) {
        int r = idx / BI, i = idx % BI;
        sA[r][i] = lA[(size_t)r * KK + i0 + i];
    }
    for (int idx = tid; idx < BO * RR; idx += 256) {
        int o = idx / RR, r = idx % RR;
        sB[o][r] = lB[(size_t)(o0 + o) * RR + r];
    }
    if (tid < BO) { sS[tid] = scale[o0 + tid]; sZ[tid] = zero[o0 + tid]; }
    __syncthreads();

    for (int idx = tid; idx < BO * BI; idx += 256) {
        int o = idx / BI, i = idx % BI;   // threads in a pass share o -> smem broadcast
        float w = ((float)wq[(size_t)(o0 + o) * KK + i0 + i] - sZ[o]) * sS[o];
        float acc = 0.f;
        #pragma unroll
        for (int r = 0; r < RR; r++) acc += sB[o][r] * sA[r][i];
        w += LORA_SCALING * acc;
        g_Weff[(size_t)(o0 + o) * KK + i0 + i] = to_tf32(w);
    }
}

// ---------------------------------------------------------------------------
// Kernel 3: C[m,n] = sum_k xr[m,k] * Weff[n,k] + bias[n]
// TF32 mma.sync m16n8k8, 128x128x32 CTA tile, 256 threads (4x2 warps),
// cp.async double-buffered shared memory with +4 padding (conflict-free).
// ---------------------------------------------------------------------------
constexpr int BMT = 128, BNT = 128, BKT = 32;
constexpr int SLD = BKT + 4;              // 36 floats per smem row
constexpr int STAGE = BMT * SLD;          // floats per stage per operand

__global__ void __launch_bounds__(256, 2)
gemm_tf32_kernel(const float* __restrict__ bias, float* __restrict__ C) {
    extern __shared__ float sm[];
    float* sAb = sm;                  // [2][128][36]
    float* sBb = sm + 2 * STAGE;      // [2][128][36]

    const int tid  = threadIdx.x;
    const int m0   = blockIdx.y * BMT;
    const int n0   = blockIdx.x * BNT;

    // ---- global->smem load mapping (per stage: 128 rows x 32 cols fp32) ----
    const int lr = tid >> 3;          // 0..31 (base row, step 32, 4 rows/thread)
    const int lc = (tid & 7) * 4;     // float4 column
    const float* gA = g_xr   + (size_t)(m0 + lr) * KK + lc;
    const float* gB = g_Weff + (size_t)(n0 + lr) * KK + lc;

    unsigned sAu = (unsigned)__cvta_generic_to_shared(sAb);
    unsigned sBu = (unsigned)__cvta_generic_to_shared(sBb);

    #define ISSUE_STAGE(kt, s) do { \
        const float* pa = gA + (size_t)(kt) * BKT; \
        const float* pb = gB + (size_t)(kt) * BKT; \
        unsigned da = sAu + (unsigned)(((s) * STAGE + lr * SLD + lc) * 4); \
        unsigned db = sBu + (unsigned)(((s) * STAGE + lr * SLD + lc) * 4); \
        _Pragma("unroll") \
        for (int rr = 0; rr < 4; rr++) { \
            CP_ASYNC16(da + rr * 32 * SLD * 4, pa + (size_t)rr * 32 * KK); \
            CP_ASYNC16(db + rr * 32 * SLD * 4, pb + (size_t)rr * 32 * KK); \
        } \
        CP_COMMIT(); \
    } while (0)

    // ---- warp/fragment mapping ----
    const int warp = tid >> 5;
    const int lane = tid & 31;
    const int wm = (warp & 3) * 32;       // warp M offset (4 warps along M)
    const int wn = (warp >> 2) * 64;      // warp N offset (2 warps along N)
    const int gid = lane >> 2;            // 0..7
    const int tig = lane & 3;             // 0..3

    float acc[2][8][4];
    #pragma unroll
    for (int a = 0; a < 2; a++)
        #pragma unroll
        for (int b = 0; b < 8; b++)
            #pragma unroll
            for (int c = 0; c < 4; c++) acc[a][b][c] = 0.f;

    ISSUE_STAGE(0, 0);

    constexpr int KT = KK / BKT;          // 128 iterations
    for (int kt = 0; kt < KT; kt++) {
        CP_WAIT0();
        __syncthreads();
        if (kt + 1 < KT) ISSUE_STAGE(kt + 1, (kt + 1) & 1);

        const float* cA = sAb + (kt & 1) * STAGE;
        const float* cB = sBb + (kt & 1) * STAGE;

        #pragma unroll
        for (int k8 = 0; k8 < 4; k8++) {
            const int kk = k8 * 8;
            unsigned af[2][4], bf[8][2];
            #pragma unroll
            for (int mi = 0; mi < 2; mi++) {
                const float* p = cA + (wm + mi * 16 + gid) * SLD + kk + tig;
                af[mi][0] = __float_as_uint(p[0]);
                af[mi][1] = __float_as_uint(p[8 * SLD]);
                af[mi][2] = __float_as_uint(p[4]);
                af[mi][3] = __float_as_uint(p[8 * SLD + 4]);
            }
            #pragma unroll
            for (int ni = 0; ni < 8; ni++) {
                const float* p = cB + (wn + ni * 8 + gid) * SLD + kk + tig;
                bf[ni][0] = __float_as_uint(p[0]);
                bf[ni][1] = __float_as_uint(p[4]);
            }
            #pragma unroll
            for (int mi = 0; mi < 2; mi++)
                #pragma unroll
                for (int ni = 0; ni < 8; ni++) {
                    asm volatile(
                        "mma.sync.aligned.m16n8k8.row.col.f32.tf32.tf32.f32 "
                        "{%0,%1,%2,%3}, {%4,%5,%6,%7}, {%8,%9}, {%0,%1,%2,%3};\n"
                        : "+f"(acc[mi][ni][0]), "+f"(acc[mi][ni][1]),
                          "+f"(acc[mi][ni][2]), "+f"(acc[mi][ni][3])
                        : "r"(af[mi][0]), "r"(af[mi][1]), "r"(af[mi][2]), "r"(af[mi][3]),
                          "r"(bf[ni][0]), "r"(bf[ni][1]));
                }
        }
        __syncthreads();
    }

    // ---- epilogue: + bias, vectorized float2 stores ----
    #pragma unroll
    for (int mi = 0; mi < 2; mi++) {
        const int row0 = m0 + wm + mi * 16 + gid;
        #pragma unroll
        for (int ni = 0; ni < 8; ni++) {
            const int col = n0 + wn + ni * 8 + tig * 2;
            const float b0 = __ldg(bias + col);
            const float b1 = __ldg(bias + col + 1);
            float2 v0 = make_float2(acc[mi][ni][0] + b0, acc[mi][ni][1] + b1);
            float2 v1 = make_float2(acc[mi][ni][2] + b0, acc[mi][ni][3] + b1);
            *(float2*)(C + (size_t)row0 * NN + col)       = v0;
            *(float2*)(C + (size_t)(row0 + 8) * NN + col) = v1;
        }
    }
    #undef ISSUE_STAGE
}

// ---------------------------------------------------------------------------
// Launch
// ---------------------------------------------------------------------------
extern "C" void kernel_launch(void* const* d_in, const int* in_sizes, int n_in,
                              void* d_out, int out_size) {
    const float* x     = (const float*)d_in[0];
    const int*   wq    = (const int*)  d_in[1];
    const float* scale = (const float*)d_in[2];
    const float* zero  = (const float*)d_in[3];
    const float* lA    = (const float*)d_in[4];
    const float* lB    = (const float*)d_in[5];
    const float* bias  = (const float*)d_in[6];
    float* out = (float*)d_out;

    // Opt-in to >48KB dynamic smem for the GEMM (idempotent, capture-safe).
    const int smem_bytes = 2 * 2 * STAGE * (int)sizeof(float);  // 73728
    cudaFuncSetAttribute(gemm_tf32_kernel,
                         cudaFuncAttributeMaxDynamicSharedMemorySize, smem_bytes);

    // 1) round x to tf32
    {
        size_t n4 = (size_t)MM * KK / 4;
        int threads = 256;
        int blocks = (int)((n4 + threads - 1) / threads);
        conv_x_kernel<<<blocks, threads>>>((const float4*)x);
    }
    // 2) build fused effective weight (dequant + LoRA), tf32-rounded
    {
        dim3 grid(KK / 256, NN / 64);
        build_weff_kernel<<<grid, 256>>>(wq, scale, zero, lA, lB);
    }
    // 3) main TF32 GEMM + bias
    {
        dim3 grid(NN / BNT, MM / BMT);   // (32, 64)
        gemm_tf32_kernel<<<grid, 256, smem_bytes>>>(bias, out);
    }
}

// round 12
// speedup vs baseline: 2.5152x; 2.5152x over previous
#include <cuda_runtime.h>
#include <cuda_fp16.h>
#include <cstdint>

// Problem dims (fixed by reference setup_inputs)
#define MM   8192      // B*S
#define NN   4096      // D_OUT
#define KK   4096      // D_IN
#define RR   16
#define LORA_SCALING 2.0f

// ---------------------------------------------------------------------------
// Device scratch (static __device__ arrays — no runtime allocation)
// ---------------------------------------------------------------------------
__device__ __half g_xh[(size_t)MM * KK];   // 64 MB: x rounded to fp16
__device__ __half g_wh[(size_t)NN * KK];   // 32 MB: fused dequant+LoRA weight, fp16

// ---------------------------------------------------------------------------
// Helpers (base PTX only — target is sm_103 without the 'a' feature set)
// ---------------------------------------------------------------------------
__device__ __forceinline__ uint32_t smem_u32(const void* p) {
    uint32_t a;
    asm("{ .reg .u64 t; cvta.to.shared.u64 t, %1; cvt.u32.u64 %0, t; }"
        : "=r"(a) : "l"(p));
    return a;
}

#define CP_ASYNC16(dst_u32, src_ptr) \
    asm volatile("cp.async.cg.shared.global [%0], [%1], 16;\n" :: "r"(dst_u32), "l"(src_ptr))
#define CP_COMMIT()   asm volatile("cp.async.commit_group;\n" ::)
#define CP_WAIT(n)    asm volatile("cp.async.wait_group %0;\n" :: "n"(n))

#define LDMATRIX_X4(r0, r1, r2, r3, addr)                                     \
    asm volatile("ldmatrix.sync.aligned.m8n8.x4.shared.b16 {%0,%1,%2,%3}, [%4];" \
        : "=r"(r0), "=r"(r1), "=r"(r2), "=r"(r3) : "r"(addr))

#define MMA16816(d, a, b)                                                      \
    asm volatile("mma.sync.aligned.m16n8k16.row.col.f32.f16.f16.f32 "          \
        "{%0,%1,%2,%3}, {%4,%5,%6,%7}, {%8,%9}, {%0,%1,%2,%3};\n"              \
        : "+f"((d)[0]), "+f"((d)[1]), "+f"((d)[2]), "+f"((d)[3])               \
        : "r"((a)[0]), "r"((a)[1]), "r"((a)[2]), "r"((a)[3]),                  \
          "r"((b)[0]), "r"((b)[1]))

// ---------------------------------------------------------------------------
// Kernel 1: x (fp32) -> fp16  (8 elems / thread, fully vectorized)
// ---------------------------------------------------------------------------
__global__ void conv_x_kernel(const float4* __restrict__ x) {
    size_t i = (size_t)blockIdx.x * blockDim.x + threadIdx.x;
    size_t n8 = (size_t)MM * KK / 8;
    if (i < n8) {
        float4 a = x[2 * i], b = x[2 * i + 1];
        __half2 h0 = __floats2half2_rn(a.x, a.y);
        __half2 h1 = __floats2half2_rn(a.z, a.w);
        __half2 h2 = __floats2half2_rn(b.x, b.y);
        __half2 h3 = __floats2half2_rn(b.z, b.w);
        uint4 o;
        o.x = *reinterpret_cast<unsigned*>(&h0);
        o.y = *reinterpret_cast<unsigned*>(&h1);
        o.z = *reinterpret_cast<unsigned*>(&h2);
        o.w = *reinterpret_cast<unsigned*>(&h3);
        ((uint4*)g_xh)[i] = o;
    }
}

// ---------------------------------------------------------------------------
// Kernel 2: W_eff = (wq - zero)*scale + 2 * B @ A  -> fp16
// ---------------------------------------------------------------------------
__global__ void build_weff_kernel(const int* __restrict__ wq,
                                  const float* __restrict__ scale,
                                  const float* __restrict__ zero,
                                  const float* __restrict__ lA,
                                  const float* __restrict__ lB) {
    constexpr int BO = 64, BI = 256;
    __shared__ float sA[RR][BI];
    __shared__ float sB[BO][RR];
    __shared__ float sS[BO], sZ[BO];

    const int i0 = blockIdx.x * BI;
    const int o0 = blockIdx.y * BO;
    const int tid = threadIdx.x;

    for (int idx = tid; idx < RR * BI; idx += 256) {
        int r = idx / BI, i = idx % BI;
        sA[r][i] = lA[(size_t)r * KK + i0 + i];
    }
    for (int idx = tid; idx < BO * RR; idx += 256) {
        int o = idx / RR, r = idx % RR;
        sB[o][r] = lB[(size_t)(o0 + o) * RR + r];
    }
    if (tid < BO) { sS[tid] = scale[o0 + tid]; sZ[tid] = zero[o0 + tid]; }
    __syncthreads();

    for (int idx = tid; idx < BO * BI / 2; idx += 256) {
        int o = idx / (BI / 2), i2 = (idx % (BI / 2)) * 2;
        const int* wrow = wq + (size_t)(o0 + o) * KK + i0;
        float z = sZ[o], s = sS[o];
        float w0 = ((float)wrow[i2] - z) * s;
        float w1 = ((float)wrow[i2 + 1] - z) * s;
        float a0 = 0.f, a1 = 0.f;
        #pragma unroll
        for (int r = 0; r < RR; r++) {
            a0 += sB[o][r] * sA[r][i2];
            a1 += sB[o][r] * sA[r][i2 + 1];
        }
        __half2 h = __floats2half2_rn(w0 + LORA_SCALING * a0, w1 + LORA_SCALING * a1);
        *reinterpret_cast<__half2*>(g_wh + (size_t)(o0 + o) * KK + i0 + i2) = h;
    }
}

// ---------------------------------------------------------------------------
// Kernel 3: fp16 mma.sync GEMM.  C[m,n] = sum_k xh[m,k]*wh[n,k] + bias[n]
// CTA tile 128x128x64, 3-stage cp.async, SW128 xor swizzle, ldmatrix frags.
// 8 warps: 4(M) x 2(N); warp tile 32x64 (2 m16-tiles x 8 n8-tiles).
// ---------------------------------------------------------------------------
constexpr int BM = 128, BN = 128, BK = 64;     // halves; BK*2 = 128B rows (SW128)
constexpr int NSTAGES = 3;
constexpr int A_ST = BM * 128;                 // 16 KB per stage
constexpr int STG = 2 * A_ST;                  // 32 KB per stage (A + B)
constexpr int GEMM_SMEM = NSTAGES * STG + 128; // + align slack
constexpr int KT = KK / BK;                    // 64

__global__ void __launch_bounds__(256, 2)
gemm_fp16_kernel(const float* __restrict__ bias, float* __restrict__ C) {
    extern __shared__ char dsm[];
    const uint32_t tile = (smem_u32(dsm) + 127u) & ~127u;   // 128B-align

    const int tid  = threadIdx.x;
    const int warp = tid >> 5;
    const int lane = tid & 31;
    const int m0 = blockIdx.y * BM;
    const int n0 = blockIdx.x * BN;

    // ---- cp.async mapping: 2048 16B chunks / 256 threads = 8 each (4 A, 4 B)
    const __half* gA = g_xh + (size_t)m0 * KK;
    const __half* gB = g_wh + (size_t)n0 * KK;
    uint32_t soff[8];   // source offset in halves (row*KK + c16*8)
    uint32_t doff[8];   // dest byte offset within stage
    #pragma unroll
    for (int j = 0; j < 8; j++) {
        int c = tid + (j & 3) * 256;          // 0..1023
        int row = c >> 3, c16 = c & 7;
        soff[j] = (uint32_t)(row * KK + c16 * 8);
        doff[j] = (uint32_t)((j < 4 ? 0 : A_ST) + row * 128 + ((c16 ^ (row & 7)) << 4));
    }

    #define ISSUE_STAGE(kt_, s_) do {                                          \
        uint32_t base_ = tile + (s_) * STG;                                    \
        _Pragma("unroll")                                                      \
        for (int j = 0; j < 4; j++)                                            \
            CP_ASYNC16(base_ + doff[j], gA + soff[j] + (kt_) * BK);            \
        _Pragma("unroll")                                                      \
        for (int j = 4; j < 8; j++)                                            \
            CP_ASYNC16(base_ + doff[j], gB + soff[j] + (kt_) * BK);            \
        CP_COMMIT();                                                           \
    } while (0)

    // ---- warp/fragment geometry ----
    const int wm = (warp & 3) * 32;        // 4 warps along M
    const int wn = (warp >> 2) * 64;       // 2 warps along N
    const int gid = lane >> 2;             // 0..7
    const int tig = lane & 3;              // 0..3
    const int l7  = lane & 7;

    // ldmatrix per-lane row byte-offsets (swizzle chunk added per k-step)
    // A (non-trans, x4): lanes 0-15 rows m0-15 (chunk +0), 16-31 same rows (chunk +1)
    uint32_t a_row[2];
    #pragma unroll
    for (int mi = 0; mi < 2; mi++)
        a_row[mi] = (uint32_t)((wm + mi * 16 + (lane & 15)) * 128);
    const uint32_t a_cx = (uint32_t)(lane >> 4);        // chunk delta 0/1
    // B (non-trans, x4): lanes 0-15 rows n0-7 (chunk +lane>>3&1), 16-31 rows n8-15
    uint32_t b_row[4];
    #pragma unroll
    for (int ng = 0; ng < 4; ng++)
        b_row[ng] = (uint32_t)((wn + ng * 16 + l7 + ((lane >> 4) << 3)) * 128);
    const uint32_t b_cx = (uint32_t)((lane >> 3) & 1);  // chunk delta 0/1

    float acc[2][8][4];
    #pragma unroll
    for (int a = 0; a < 2; a++)
        #pragma unroll
        for (int b = 0; b < 8; b++)
            #pragma unroll
            for (int c = 0; c < 4; c++) acc[a][b][c] = 0.f;

    ISSUE_STAGE(0, 0);
    ISSUE_STAGE(1, 1);

    int s = 0;
    for (int kt = 0; kt < KT; kt++) {
        CP_WAIT(1);                       // oldest pending group (stage kt) done
        __syncthreads();                  // also fences reuse of stage (kt-1)%3
        if (kt + 2 < KT) {
            int sn = s + 2; if (sn >= NSTAGES) sn -= NSTAGES;
            ISSUE_STAGE(kt + 2, sn);
        }

        const uint32_t sA = tile + s * STG;
        const uint32_t sB = sA + A_ST;

        #pragma unroll
        for (int ks = 0; ks < 4; ks++) {          // 4 x k16 per BK=64
            const uint32_t kc = (uint32_t)(ks * 2);
            uint32_t af[2][4], bf[8][2];
            #pragma unroll
            for (int mi = 0; mi < 2; mi++) {
                uint32_t addr = sA + a_row[mi] + (((kc + a_cx) ^ l7) << 4);
                LDMATRIX_X4(af[mi][0], af[mi][1], af[mi][2], af[mi][3], addr);
            }
            #pragma unroll
            for (int ng = 0; ng < 4; ng++) {
                uint32_t addr = sB + b_row[ng] + (((kc + b_cx) ^ l7) << 4);
                LDMATRIX_X4(bf[2 * ng][0], bf[2 * ng][1],
                            bf[2 * ng + 1][0], bf[2 * ng + 1][1], addr);
            }
            #pragma unroll
            for (int mi = 0; mi < 2; mi++)
                #pragma unroll
                for (int ni = 0; ni < 8; ni++)
                    MMA16816(acc[mi][ni], af[mi], bf[ni]);
        }
        if (++s == NSTAGES) s = 0;
    }

    // ---- epilogue: + bias, float2 stores ----
    #pragma unroll
    for (int mi = 0; mi < 2; mi++) {
        const int row0 = m0 + wm + mi * 16 + gid;
        #pragma unroll
        for (int ni = 0; ni < 8; ni++) {
            const int col = n0 + wn + ni * 8 + tig * 2;
            const float b0 = __ldg(bias + col);
            const float b1 = __ldg(bias + col + 1);
            float2 v0 = make_float2(acc[mi][ni][0] + b0, acc[mi][ni][1] + b1);
            float2 v1 = make_float2(acc[mi][ni][2] + b0, acc[mi][ni][3] + b1);
            *(float2*)(C + (size_t)row0 * NN + col)       = v0;
            *(float2*)(C + (size_t)(row0 + 8) * NN + col) = v1;
        }
    }
    #undef ISSUE_STAGE
}

// ---------------------------------------------------------------------------
// Launch
// ---------------------------------------------------------------------------
extern "C" void kernel_launch(void* const* d_in, const int* in_sizes, int n_in,
                              void* d_out, int out_size) {
    const float* x     = (const float*)d_in[0];
    const int*   wq    = (const int*)  d_in[1];
    const float* scale = (const float*)d_in[2];
    const float* zero  = (const float*)d_in[3];
    const float* lA    = (const float*)d_in[4];
    const float* lB    = (const float*)d_in[5];
    const float* bias  = (const float*)d_in[6];
    float* out = (float*)d_out;

    cudaFuncSetAttribute(gemm_fp16_kernel,
                         cudaFuncAttributeMaxDynamicSharedMemorySize, GEMM_SMEM);

    // 1) x -> fp16
    {
        size_t n8 = (size_t)MM * KK / 8;
        conv_x_kernel<<<(int)((n8 + 255) / 256), 256>>>((const float4*)x);
    }
    // 2) fused dequant + LoRA -> fp16 effective weight
    {
        dim3 grid(KK / 256, NN / 64);
        build_weff_kernel<<<grid, 256>>>(wq, scale, zero, lA, lB);
    }
    // 3) fp16 tensor-core GEMM + bias
    {
        dim3 grid(NN / BN, MM / BM);   // (32, 64)
        gemm_fp16_kernel<<<grid, 256, GEMM_SMEM>>>(bias, out);
    }
}